// round 17
// baseline (speedup 1.0000x reference)
#include <cuda_runtime.h>
#include <cstdint>

#define NB  8
#define SEQ 2048
#define HID 256
#define BM  64
#define BN  256
#define QKSCALE 0.0625f

typedef unsigned long long ull;

__device__ __forceinline__ uint32_t smem_u32(const void* p){
    uint32_t a;
    asm("{ .reg .u64 t; cvta.to.shared.u64 t, %1; cvt.u32.u64 %0, t; }" : "=r"(a) : "l"(p));
    return a;
}
// round fp32 -> tf32 (RN, unbiased)
__device__ __forceinline__ float tf32r(float x){
    uint32_t u; asm("cvt.rna.tf32.f32 %0, %1;" : "=r"(u) : "f"(x));
    return __uint_as_float(u);
}
__device__ __forceinline__ uint32_t tf32u(float x){
    uint32_t u; asm("cvt.rna.tf32.f32 %0, %1;" : "=r"(u) : "f"(x));
    return u;
}
#define CPASYNC16(dst, src) \
    asm volatile("cp.async.cg.shared.global [%0], [%1], 16;" :: "r"(dst), "l"(src) : "memory")
#define CP_COMMIT()  asm volatile("cp.async.commit_group;" ::: "memory")
#define CP_WAIT(n)   asm volatile("cp.async.wait_group %0;" :: "n"(n) : "memory")

// m16n8k8 tf32 mma
__device__ __forceinline__ void mma8(float* c,
    uint32_t a0, uint32_t a1, uint32_t a2, uint32_t a3, uint32_t b0, uint32_t b1)
{
    asm volatile("mma.sync.aligned.m16n8k8.row.col.f32.tf32.tf32.f32 "
        "{%0,%1,%2,%3}, {%4,%5,%6,%7}, {%8,%9}, {%0,%1,%2,%3};"
        : "+f"(c[0]), "+f"(c[1]), "+f"(c[2]), "+f"(c[3])
        : "r"(a0), "r"(a1), "r"(a2), "r"(a3), "r"(b0), "r"(b1));
}
#define F2U(x) __float_as_uint(x)

// projection outputs (device-global scratch).
// g_Q, g_K: [b,s,h], h permuted within each 8-block (pos(j) = 2j if j<4 else 2(j-4)+1)
// g_V:      [b,h,s] transposed, s permuted within each 8-block (same map)
__device__ float g_Q[NB*SEQ*HID];
__device__ float g_K[NB*SEQ*HID];
__device__ float g_V[NB*SEQ*HID];

// ============================================================================
// Projection via tf32 mma.sync (round-14 version, verbatim; ~69us).
// smem: Ws[128][260] | As 2x[128][36]   (T[128][140] reuses Ws region)
// ============================================================================
#define PWSTR 260
#define PASTR 36
#define P_OFF_A 33280
#define P_ASLOT 4608
#define P_SMEM ((33280 + 2*4608) * 4)
#define TSTR 140

__global__ void __launch_bounds__(256, 1)
proj_kernel(const float* __restrict__ q, const float* __restrict__ k, const float* __restrict__ v,
            const float* __restrict__ Wq, const float* __restrict__ Wk, const float* __restrict__ Wv)
{
    extern __shared__ float psm[];
    float* Ws = psm;
    float* As = psm + P_OFF_A;
    const uint32_t sA = smem_u32(As);

    const float* X; const float* W; float* Y;
    if (blockIdx.z == 0)      { X = q; W = Wq; Y = g_Q; }
    else if (blockIdx.z == 1) { X = k; W = Wk; Y = g_K; }
    else                      { X = v; W = Wv; Y = g_V; }
    const bool isV = (blockIdx.z == 2);

    const int tid = threadIdx.x;
    const int wid = tid >> 5, lane = tid & 31;
    const int rg = wid >> 1, cg = wid & 1;
    const int r0 = rg * 32, c0 = cg * 64;
    const int g = lane >> 2, tg = lane & 3;
    const int m0 = blockIdx.y * 128;
    const int n0 = blockIdx.x * 128;

    // issue A chunk 0 (slot 0)
    #pragma unroll
    for (int p = 0; p < 4; p++){
        int flat = tid + 256*p;
        int r = flat >> 3, j = flat & 7;
        CPASYNC16(sA + (r*PASTR + j*4)*4, (const void*)&X[(size_t)(m0 + r)*HID + j*4]);
    }
    CP_COMMIT();

    // W transpose into Ws[n][k], RN-rounded to tf32 (coalesced LDG rows)
    {
        const int n = (wid & 3)*32 + lane;
        const int kq0 = wid >> 2;
        #pragma unroll 4
        for (int i = 0; i < 32; i++){
            int kq = kq0 + 2*i;
            float a0 = W[(size_t)(kq*4+0)*HID + n0 + n];
            float a1 = W[(size_t)(kq*4+1)*HID + n0 + n];
            float a2 = W[(size_t)(kq*4+2)*HID + n0 + n];
            float a3 = W[(size_t)(kq*4+3)*HID + n0 + n];
            *(float4*)&Ws[n*PWSTR + kq*4] =
                make_float4(tf32r(a0), tf32r(a1), tf32r(a2), tf32r(a3));
        }
    }

    float acc[2][8][4];
    #pragma unroll
    for (int mi = 0; mi < 2; mi++)
        #pragma unroll
        for (int nt = 0; nt < 8; nt++)
            #pragma unroll
            for (int j = 0; j < 4; j++) acc[mi][nt][j] = 0.f;

    #pragma unroll 1
    for (int kc = 0; kc < 8; kc++){
        CP_WAIT(0);
        __syncthreads();           // publishes chunk kc (and Ws on kc==0)
        if (kc < 7){
            const uint32_t dst = sA + (((kc+1)&1)*P_ASLOT)*4;
            #pragma unroll
            for (int p = 0; p < 4; p++){
                int flat = tid + 256*p;
                int r = flat >> 3, j = flat & 7;
                CPASYNC16(dst + (r*PASTR + j*4)*4,
                          (const void*)&X[(size_t)(m0 + r)*HID + (kc+1)*32 + j*4]);
            }
            CP_COMMIT();
        }
        const float* Ab = As + (kc&1)*P_ASLOT;
        #pragma unroll
        for (int ks = 0; ks < 4; ks++){
            int kk = ks*8;
            uint32_t a[2][4];
            #pragma unroll
            for (int mi = 0; mi < 2; mi++){
                int base = (r0 + 16*mi + g)*PASTR + kk + tg;
                a[mi][0] = tf32u(Ab[base]);
                a[mi][1] = tf32u(Ab[base + 8*PASTR]);
                a[mi][2] = tf32u(Ab[base + 4]);
                a[mi][3] = tf32u(Ab[base + 8*PASTR + 4]);
            }
            #pragma unroll
            for (int nt = 0; nt < 8; nt++){
                int c = c0 + nt*8 + g;
                uint32_t b0 = F2U(Ws[c*PWSTR + kc*32 + kk + tg]);
                uint32_t b1 = F2U(Ws[c*PWSTR + kc*32 + kk + tg + 4]);
                mma8(acc[0][nt], a[0][0], a[0][1], a[0][2], a[0][3], b0, b1);
                mma8(acc[1][nt], a[1][0], a[1][1], a[1][2], a[1][3], b0, b1);
            }
        }
    }
    __syncthreads();   // all reads of Ws/As done before T overwrites (V path)

    // within-8 position map: pos(j) = 2j (j<4) else 2(j-4)+1
    const int pA = (tg < 2) ? 4*tg : 4*tg - 7;
    const int pB = pA + 2;
    const int pg = (g < 4) ? 2*g : 2*(g-4) + 1;

    if (!isV){
        #pragma unroll
        for (int mi = 0; mi < 2; mi++){
            int row = m0 + r0 + 16*mi + g;
            #pragma unroll
            for (int nt = 0; nt < 8; nt++){
                int colb = n0 + c0 + nt*8;
                Y[(size_t)row*HID + colb + pA]     = tf32r(acc[mi][nt][0]);
                Y[(size_t)row*HID + colb + pB]     = tf32r(acc[mi][nt][1]);
                Y[(size_t)(row+8)*HID + colb + pA] = tf32r(acc[mi][nt][2]);
                Y[(size_t)(row+8)*HID + colb + pB] = tf32r(acc[mi][nt][3]);
            }
        }
    } else {
        // V: stage O^T in smem (s-pair-permuted m positions), then coalesced STG
        float* T = psm;   // [128 n][TSTR], reuses Ws region
        #pragma unroll
        for (int mi = 0; mi < 2; mi++){
            int mb = r0 + 16*mi;
            #pragma unroll
            for (int nt = 0; nt < 8; nt++){
                int n = c0 + nt*8 + 2*tg;
                T[n*TSTR     + mb + pg]     = tf32r(acc[mi][nt][0]);
                T[(n+1)*TSTR + mb + pg]     = tf32r(acc[mi][nt][1]);
                T[n*TSTR     + mb + 8 + pg] = tf32r(acc[mi][nt][2]);
                T[(n+1)*TSTR + mb + 8 + pg] = tf32r(acc[mi][nt][3]);
            }
        }
        __syncthreads();
        const int bb = m0 >> 11;
        const int sbase = m0 & 2047;
        #pragma unroll 4
        for (int i = 0; i < 16; i++){
            int n = wid*16 + i;
            float4 vv = *(const float4*)&T[n*TSTR + 4*lane];
            *(float4*)&Y[(size_t)bb*SEQ*HID + (size_t)(n0 + n)*SEQ + sbase + 4*lane] = vv;
        }
    }
}

// ============================================================================
// Flash attention via mma.sync tf32 — 256 threads, 8 warps (2 rg x 4 cq),
// warp tile 32x64: each b-fragment LDS.64 feeds TWO m16 MMAs, cutting
// crossbar bytes 1.63x vs round 14. All fragment loads LDS.64 (pair-permuted
// gmem layouts). K/V tiles [256][32] @ stride 40; Qs/Ps stride 264.
// 2 slots, ONE sync per chunk. No-max softmax; P tf32-rounded.
// smem (floats): Qs[64][264] | Ps[64][264] | KV 2x10240 | lp[64][4]
// ============================================================================
#define QSTR 264
#define KVSTR 40
#define O_PS 16896
#define O_KV 33792
#define KVSLOT 10240
#define O_LP 54272
#define SMEM_ATTN (54528 * 4)

__global__ void __launch_bounds__(256, 1)
attn_kernel(const uint32_t* __restrict__ mask, float* __restrict__ out)
{
    extern __shared__ float sm[];
    float* Qs = sm;
    float* Ps = sm + O_PS;
    float* KV = sm + O_KV;
    float* lp = sm + O_LP;
    const uint32_t sQ  = smem_u32(Qs);
    const uint32_t sKV = smem_u32(KV);

    const int tid  = threadIdx.x;
    const int wid  = tid >> 5, lane = tid & 31;
    const int rg   = wid >> 2, cq = wid & 3;
    const int r0   = rg * 32;                 // 32 q-rows per warp
    const int c0   = cq * 64;
    const int g    = lane >> 2, tg = lane & 3;
    const int b    = blockIdx.y;
    const int q0   = blockIdx.x * BM;

    const float* Qg = g_Q + (size_t)b*SEQ*HID;
    const float* Kg = g_K + (size_t)b*SEQ*HID;
    const float* Vg = g_V + (size_t)b*SEQ*HID;   // [h][s] layout
    const uint32_t* Mg = mask + (size_t)b*SEQ*SEQ;

    // ---- load Q tile [64][256] -> Qs[64][264] (already pair-permuted) ----
    #pragma unroll
    for (int p = 0; p < 16; p++){
        int idx = tid + 256*p;
        int r = idx >> 6, j = idx & 63;
        CPASYNC16(sQ + (r*QSTR + j*4)*4, (const void*)&Qg[(size_t)(q0 + r)*HID + j*4]);
    }
    CP_COMMIT();

    float oacc[2][8][4];
    #pragma unroll
    for (int mi = 0; mi < 2; mi++)
        #pragma unroll
        for (int i = 0; i < 8; i++)
            #pragma unroll
            for (int j = 0; j < 4; j++) oacc[mi][i][j] = 0.f;
    float lsum[4] = {0.f, 0.f, 0.f, 0.f};

    CP_WAIT(0);
    __syncthreads();

    for (int t = 0; t < SEQ/BN; t++){
        const int k0 = t * BN;

        // ===== QK^T: 8 hid-chunks of 32, 2 slots, ONE sync per chunk =====
        float sacc[2][8][4];
        #pragma unroll
        for (int mi = 0; mi < 2; mi++)
            #pragma unroll
            for (int i = 0; i < 8; i++)
                #pragma unroll
                for (int j = 0; j < 4; j++) sacc[mi][i][j] = 0.f;

        // preamble: K chunk 0 -> slot 0 ([c=256][32] @ stride 40)
        #pragma unroll
        for (int p = 0; p < 8; p++){
            int flat = tid + 256*p;
            int c = flat >> 3, j = flat & 7;
            CPASYNC16(sKV + (c*KVSTR + j*4)*4,
                      (const void*)&Kg[(size_t)(k0 + c)*HID + j*4]);
        }
        CP_COMMIT();

        #pragma unroll 1
        for (int hc = 0; hc < 8; hc++){
            CP_WAIT(0);
            __syncthreads();       // chunk hc visible; everyone past compute hc-1
            if (hc < 7){
                const uint32_t dst = sKV + (((hc+1)&1)*KVSLOT)*4;
                #pragma unroll
                for (int p = 0; p < 8; p++){
                    int flat = tid + 256*p;
                    int c = flat >> 3, j = flat & 7;
                    CPASYNC16(dst + (c*KVSTR + j*4)*4,
                              (const void*)&Kg[(size_t)(k0 + c)*HID + (hc+1)*32 + j*4]);
                }
                CP_COMMIT();
            }
            const float* Kb = KV + (hc&1)*KVSLOT;
            #pragma unroll
            for (int ks = 0; ks < 4; ks++){
                int kk = ks*8;
                int hb = hc*32 + kk;
                uint32_t a[2][4];
                #pragma unroll
                for (int mi = 0; mi < 2; mi++){
                    float2 aA = *(const float2*)&Qs[(r0+16*mi+g  )*QSTR + hb + 2*tg];
                    float2 aB = *(const float2*)&Qs[(r0+16*mi+8+g)*QSTR + hb + 2*tg];
                    a[mi][0] = F2U(aA.x); a[mi][1] = F2U(aB.x);
                    a[mi][2] = F2U(aA.y); a[mi][3] = F2U(aB.y);
                }
                #pragma unroll
                for (int nt = 0; nt < 8; nt++){
                    int c = c0 + nt*8 + g;
                    float2 bb = *(const float2*)&Kb[c*KVSTR + kk + 2*tg];
                    uint32_t b0 = F2U(bb.x), b1 = F2U(bb.y);
                    mma8(sacc[0][nt], a[0][0], a[0][1], a[0][2], a[0][3], b0, b1);
                    mma8(sacc[1][nt], a[1][0], a[1][1], a[1][2], a[1][3], b0, b1);
                }
            }
        }

        // V chunk 0 -> slot 0 (Vt [h=256][32] @ stride 40; slot held K chunk 6)
        #pragma unroll
        for (int p = 0; p < 8; p++){
            int flat = tid + 256*p;
            int h = flat >> 3, j = flat & 7;
            CPASYNC16(sKV + (h*KVSTR + j*4)*4,
                      (const void*)&Vg[(size_t)h*SEQ + k0 + 4*j]);
        }
        CP_COMMIT();

        // ===== softmax (no max): P = mask ? 0 : tf32(exp(S/16)), s-permuted =====
        {
            const int pA = (tg < 2) ? 4*tg : 4*tg - 7;
            #pragma unroll
            for (int mi = 0; mi < 2; mi++){
                const uint32_t* mr0 = Mg + (size_t)(q0 + r0 + 16*mi + g)*SEQ + k0 + c0 + 2*tg;
                const uint32_t* mr1 = mr0 + 8*SEQ;
                #pragma unroll
                for (int nt = 0; nt < 8; nt++){
                    uint2 m0v = *(const uint2*)(mr0 + nt*8);
                    uint2 m1v = *(const uint2*)(mr1 + nt*8);
                    float p00 = m0v.x ? 0.f : tf32r(__expf(sacc[mi][nt][0] * QKSCALE));
                    float p01 = m0v.y ? 0.f : tf32r(__expf(sacc[mi][nt][1] * QKSCALE));
                    float p10 = m1v.x ? 0.f : tf32r(__expf(sacc[mi][nt][2] * QKSCALE));
                    float p11 = m1v.y ? 0.f : tf32r(__expf(sacc[mi][nt][3] * QKSCALE));
                    lsum[2*mi]   += p00 + p01;
                    lsum[2*mi+1] += p10 + p11;
                    int colb = c0 + nt*8;
                    Ps[(r0+16*mi+g  )*QSTR + colb + pA]     = p00;
                    Ps[(r0+16*mi+g  )*QSTR + colb + pA + 2] = p01;
                    Ps[(r0+16*mi+8+g)*QSTR + colb + pA]     = p10;
                    Ps[(r0+16*mi+8+g)*QSTR + colb + pA + 2] = p11;
                }
            }
        }

        // ===== P @ V: 8 s-chunks of 32, 2 slots, ONE sync per chunk =====
        #pragma unroll 1
        for (int cc = 0; cc < 8; cc++){
            CP_WAIT(0);
            __syncthreads();       // V chunk cc visible; Ps published (cc==0)
            if (cc < 7){
                const uint32_t dst = sKV + (((cc+1)&1)*KVSLOT)*4;
                #pragma unroll
                for (int p = 0; p < 8; p++){
                    int flat = tid + 256*p;
                    int h = flat >> 3, j = flat & 7;
                    CPASYNC16(dst + (h*KVSTR + j*4)*4,
                              (const void*)&Vg[(size_t)h*SEQ + k0 + (cc+1)*32 + 4*j]);
                }
                CP_COMMIT();
            }
            const float* Vb = KV + (cc&1)*KVSLOT;
            #pragma unroll
            for (int ks = 0; ks < 4; ks++){
                int kk = ks*8;
                int cb = cc*32 + kk;
                uint32_t a[2][4];
                #pragma unroll
                for (int mi = 0; mi < 2; mi++){
                    float2 pAf = *(const float2*)&Ps[(r0+16*mi+g  )*QSTR + cb + 2*tg];
                    float2 pBf = *(const float2*)&Ps[(r0+16*mi+8+g)*QSTR + cb + 2*tg];
                    a[mi][0] = F2U(pAf.x); a[mi][1] = F2U(pBf.x);
                    a[mi][2] = F2U(pAf.y); a[mi][3] = F2U(pBf.y);
                }
                #pragma unroll
                for (int nt = 0; nt < 8; nt++){
                    int h = c0 + nt*8 + g;
                    float2 vv = *(const float2*)&Vb[h*KVSTR + kk + 2*tg];
                    uint32_t b0 = F2U(vv.x), b1 = F2U(vv.y);
                    mma8(oacc[0][nt], a[0][0], a[0][1], a[0][2], a[0][3], b0, b1);
                    mma8(oacc[1][nt], a[1][0], a[1][1], a[1][2], a[1][3], b0, b1);
                }
            }
        }
    }

    // ===== epilogue: l reduce + O /= l (fully-masked rows -> 0) =====
    #pragma unroll
    for (int i = 0; i < 4; i++){
        lsum[i] += __shfl_xor_sync(0xffffffffu, lsum[i], 1);
        lsum[i] += __shfl_xor_sync(0xffffffffu, lsum[i], 2);
    }
    if (tg == 0){
        #pragma unroll
        for (int mi = 0; mi < 2; mi++){
            lp[(r0+16*mi+g  )*4 + cq] = lsum[2*mi];
            lp[(r0+16*mi+8+g)*4 + cq] = lsum[2*mi+1];
        }
    }
    __syncthreads();
    #pragma unroll
    for (int mi = 0; mi < 2; mi++){
        int rowA = r0 + 16*mi + g;
        int rowB = rowA + 8;
        float l0 = lp[rowA*4] + lp[rowA*4+1] + lp[rowA*4+2] + lp[rowA*4+3];
        float l1 = lp[rowB*4] + lp[rowB*4+1] + lp[rowB*4+2] + lp[rowB*4+3];
        float inv0 = (l0 > 0.f) ? (1.f/l0) : 0.f;
        float inv1 = (l1 > 0.f) ? (1.f/l1) : 0.f;
        float* or0 = out + (size_t)(b*SEQ + q0 + rowA)*HID;
        float* or1 = out + (size_t)(b*SEQ + q0 + rowB)*HID;
        #pragma unroll
        for (int nt = 0; nt < 8; nt++){
            int h = c0 + nt*8 + 2*tg;       // O columns are natural h
            *(float2*)&or0[h] = make_float2(oacc[mi][nt][0]*inv0, oacc[mi][nt][1]*inv0);
            *(float2*)&or1[h] = make_float2(oacc[mi][nt][2]*inv1, oacc[mi][nt][3]*inv1);
        }
    }
}

// ============================================================================
extern "C" void kernel_launch(void* const* d_in, const int* in_sizes, int n_in,
                              void* d_out, int out_size)
{
    (void)in_sizes; (void)n_in; (void)out_size;
    const float* k  = (const float*)d_in[0];
    const float* q  = (const float*)d_in[1];
    const float* v  = (const float*)d_in[2];
    const uint32_t* mask = (const uint32_t*)d_in[3];
    const float* Wq = (const float*)d_in[4];
    const float* Wk = (const float*)d_in[5];
    const float* Wv = (const float*)d_in[6];
    float* out = (float*)d_out;

    cudaFuncSetAttribute(proj_kernel,
                         cudaFuncAttributeMaxDynamicSharedMemorySize, P_SMEM);
    proj_kernel<<<dim3(2, 128, 3), 256, P_SMEM>>>(q, k, v, Wq, Wk, Wv);

    cudaFuncSetAttribute(attn_kernel,
                         cudaFuncAttributeMaxDynamicSharedMemorySize, SMEM_ATTN);
    attn_kernel<<<dim3(SEQ/BM, NB), 256, SMEM_ATTN>>>(mask, out);
}